// round 16
// baseline (speedup 1.0000x reference)
#include <cuda_runtime.h>
#include <cuda_bf16.h>
#include <math.h>
#include <stdint.h>

// ---------------------------------------------------------------------------
// Problem constants
// ---------------------------------------------------------------------------
#define BATCH   8192
#define IN_DIM  4096
#define OUT_DIM 2048
#define DEPTH   9
#define RSTEPS  27
#define WIN     55
#define CENTER  27

// GEMM tiling: 128x64 CTA tile, BK=64, 2-stage ring, 2 CTAs/SM
#define BM 128
#define BN 64
#define BK 64
#define NKT (IN_DIM / BK)            // 64
#define STAGES 2
// Stage layout (128B rows): Ahi 16K | Alo 16K | Bhi 8K | Blo 8K
#define AHI 0
#define ALO 16384
#define BHI 32768
#define BLO 40960
#define STAGE_BYTES 49152
#define SMEM_TOTAL (STAGES * STAGE_BYTES)   // 98304/CTA -> 2 CTAs = 192KB/SM

// ---------------------------------------------------------------------------
// Device-global scratch (static: no runtime allocation)
// ---------------------------------------------------------------------------
__device__ float         g_pb[OUT_DIM];
__device__ __nv_bfloat16 g_xhi[(size_t)BATCH * IN_DIM];
__device__ __nv_bfloat16 g_xlo[(size_t)BATCH * IN_DIM];
__device__ __nv_bfloat16 g_wThi[(size_t)OUT_DIM * IN_DIM];   // W^T [N][K]
__device__ __nv_bfloat16 g_wTlo[(size_t)OUT_DIM * IN_DIM];

// ---------------------------------------------------------------------------
// PTX helpers (base sm_103 ISA only: cp.async / ldmatrix / mma.sync)
// ---------------------------------------------------------------------------
__device__ __forceinline__ uint32_t smem_u32(const void* p) {
    uint32_t a;
    asm("{ .reg .u64 t; cvta.to.shared.u64 t, %1; cvt.u32.u64 %0, t; }"
        : "=r"(a) : "l"(p));
    return a;
}
__device__ __forceinline__ void cpasync16(uint32_t dst, const void* src) {
    asm volatile("cp.async.cg.shared.global [%0], [%1], 16;"
                 :: "r"(dst), "l"(src));
}
#define CP_COMMIT() asm volatile("cp.async.commit_group;" ::: "memory")
#define CP_WAIT0()  asm volatile("cp.async.wait_group 0;"  ::: "memory")

#define LDSM_X4(d, a) \
    asm volatile("ldmatrix.sync.aligned.m8n8.x4.shared.b16 {%0,%1,%2,%3}, [%4];" \
        : "=r"((d)[0]), "=r"((d)[1]), "=r"((d)[2]), "=r"((d)[3]) : "r"(a))

#define MMA16816(c, a, b) \
    asm volatile("mma.sync.aligned.m16n8k16.row.col.f32.bf16.bf16.f32 " \
        "{%0,%1,%2,%3}, {%4,%5,%6,%7}, {%8,%9}, {%0,%1,%2,%3};" \
        : "+f"((c)[0]), "+f"((c)[1]), "+f"((c)[2]), "+f"((c)[3]) \
        : "r"((a)[0]), "r"((a)[1]), "r"((a)[2]), "r"((a)[3]), \
          "r"((b)[0]), "r"((b)[1]))

// SW128 swizzle for 128B physical rows: row r, 16B-chunk cc in 0..7.
__device__ __forceinline__ uint32_t swz128(uint32_t base, int row, int cc) {
    return base + row * 128 + (((cc) ^ (row & 7)) << 4);
}

// ---------------------------------------------------------------------------
// Fused prepass kernel: one launch, roles by blockIdx.x range.
//   [0, 16384)            split x -> (hi, lo) bf16   (8 elems/thread, 16B stores)
//   [16384, 24576)        transpose+split W -> wT hi/lo (4-wide 8B stores)
//   [24576, 24584)        universal probs + bias -> g_pb
// ---------------------------------------------------------------------------
#define SPLITX_BLOCKS 16384   // (8192*4096)/(8*256)
#define SPLITW_BLOCKS 8192    // (2048/32)*(4096/32)
#define PROBS_BLOCKS  8
#define PREP_BLOCKS   (SPLITX_BLOCKS + SPLITW_BLOCKS + PROBS_BLOCKS)

__device__ __forceinline__ uint32_t split_pair(float a, float b, uint32_t* lo) {
    __nv_bfloat16 ha = __float2bfloat16(a);
    __nv_bfloat16 hb = __float2bfloat16(b);
    __nv_bfloat162 hp(ha, hb);
    __nv_bfloat162 lp(__float2bfloat16(a - __bfloat162float(ha)),
                      __float2bfloat16(b - __bfloat162float(hb)));
    *lo = *(uint32_t*)&lp;
    return *(uint32_t*)&hp;
}

__global__ __launch_bounds__(256)
void prep_kernel(const float* __restrict__ x,
                 const float* __restrict__ W,
                 const float* __restrict__ uw,
                 const float* __restrict__ bias) {
    __shared__ float t[32][33];
    const int b   = blockIdx.x;
    const int tid = threadIdx.x;

    if (b < SPLITX_BLOCKS) {
        // ---- split x: 8 elements/thread, 16B hi store + 16B lo store ----
        size_t i = ((size_t)b * 256 + tid) * 8;
        float4 v0 = *(const float4*)(x + i);
        float4 v1 = *(const float4*)(x + i + 4);
        uint4 hi, lo;
        hi.x = split_pair(v0.x, v0.y, &lo.x);
        hi.y = split_pair(v0.z, v0.w, &lo.y);
        hi.z = split_pair(v1.x, v1.y, &lo.z);
        hi.w = split_pair(v1.z, v1.w, &lo.w);
        *(uint4*)(g_xhi + i) = hi;
        *(uint4*)(g_xlo + i) = lo;
    } else if (b < SPLITX_BLOCKS + SPLITW_BLOCKS) {
        // ---- transpose + split W (vectorized output: 4 k per thread) ----
        const int bw = b - SPLITX_BLOCKS;
        const int n0 = (bw & 63) * 32;
        const int k0 = (bw >> 6) * 32;
        const int tx = tid & 31, ty = tid >> 5;   // 32 x 8 load mapping
#pragma unroll
        for (int i = 0; i < 32; i += 8)
            t[ty + i][tx] = W[(size_t)(k0 + ty + i) * OUT_DIM + n0 + tx];
        __syncthreads();
        // Store mapping: thread = (row n = tid&31, k-quad q = tid>>5)
        const int n = tid & 31;
        const int q = (tid >> 5) * 4;             // k offset 0,4,...,28
        uint32_t h2[2], l2[2];
#pragma unroll
        for (int j = 0; j < 2; j++) {
            float a = t[q + j * 2][n];
            float c = t[q + j * 2 + 1][n];
            h2[j] = split_pair(a, c, &l2[j]);
        }
        size_t o = (size_t)(n0 + n) * IN_DIM + k0 + q;
        *(uint2*)(g_wThi + o) = make_uint2(h2[0], h2[1]);
        *(uint2*)(g_wTlo + o) = make_uint2(l2[0], l2[1]);
    } else {
        // ---- universal probs (dependency-cone trick) ----
        const int o = (b - SPLITX_BLOCKS - SPLITW_BLOCKS) * 256 + tid;
        if (o >= OUT_DIM) return;
        float w[WIN];
#pragma unroll
        for (int j = 0; j < WIN; j++) w[j] = 0.015625f;   // 1/sqrt(4096)
#pragma unroll
        for (int s = 0; s < RSTEPS; s++) {
            const int d = s / 3, g = s % 3;
            float ang = uw[(size_t)d * IN_DIM * OUT_DIM + (size_t)o * OUT_DIM + g];
            float sn, cs;
            sincosf(ang, &sn, &cs);
            float nw[WIN];
            nw[0] = w[0]; nw[WIN - 1] = w[WIN - 1];
#pragma unroll
            for (int j = 1; j < WIN - 1; j++)
                nw[j] = cs * w[j] - sn * w[j + 1] + sn * w[j - 1];
#pragma unroll
            for (int j = 0; j < WIN; j++) w[j] = nw[j];
        }
        g_pb[o] = w[CENTER] * w[CENTER] + bias[o];
    }
}

// ---------------------------------------------------------------------------
// GEMM kernel: C = tanh(x @ W + g_pb) via bf16x3 mma.sync.
// 128x64x64 chunks, 2-stage ring, 2 CTAs/SM, 8 warps, warp tile 32x32.
// ONE wait0+__syncthreads per BK=64 chunk; no cross-stage reads.
// R16: refill spread as THREE 4-op cp.async bursts (A-lo-rows after phase 0,
// A-hi-rows after phase 1, B after phase 2), each with its own commit —
// wait_group 0 at the top waits ALL groups, so per-burst commits are safe.
// Running kload pointer offsets (no per-chunk multiplies).
// ---------------------------------------------------------------------------
__global__ __launch_bounds__(256, 2)
void gemm_bf16x3_kernel(float* __restrict__ out) {
    extern __shared__ char smem[];
    const uint32_t sb = smem_u32(smem);

    const int tid  = threadIdx.x;
    const int lane = tid & 31;
    const int wid  = tid >> 5;
    const int wm   = wid >> 1;          // 0..3  -> m offset wm*32
    const int wn   = wid & 1;           // 0..1  -> n offset wn*32
    const int gid  = lane >> 2;
    const int tg   = lane & 3;
    const int bm   = blockIdx.y * BM;
    const int bn   = blockIdx.x * BN;

    // --- global load mapping: 12 x 16B chunks per thread per BK=64 chunk ---
    const int r0 = tid >> 3;            // 0..31
    const int cA = tid & 7;             // 16B chunk in 128B row

    const __nv_bfloat16* pAh = g_xhi  + (size_t)(bm + r0) * IN_DIM + cA * 8;
    const __nv_bfloat16* pAl = g_xlo  + (size_t)(bm + r0) * IN_DIM + cA * 8;
    const __nv_bfloat16* pBh = g_wThi + (size_t)(bn + r0) * IN_DIM + cA * 8;
    const __nv_bfloat16* pBl = g_wTlo + (size_t)(bn + r0) * IN_DIM + cA * 8;

    const uint32_t dAh = swz128(AHI, r0, cA);
    const uint32_t dAl = swz128(ALO, r0, cA);
    const uint32_t dBh = swz128(BHI, r0, cA);
    const uint32_t dBl = swz128(BLO, r0, cA);

    // Burst 1: A rows 0..63 (hi+lo), Burst 2: A rows 64..127, Burst 3: B.
#define ISSUE_A0(stg, ko)                                                    \
    do {                                                                     \
        uint32_t s_ = sb + (stg) * STAGE_BYTES;                              \
        cpasync16(s_ + dAh,        pAh + (ko));                              \
        cpasync16(s_ + dAl,        pAl + (ko));                              \
        cpasync16(s_ + dAh + 4096, pAh + (ko) + (size_t)32 * IN_DIM);        \
        cpasync16(s_ + dAl + 4096, pAl + (ko) + (size_t)32 * IN_DIM);        \
    } while (0)
#define ISSUE_A1(stg, ko)                                                    \
    do {                                                                     \
        uint32_t s_ = sb + (stg) * STAGE_BYTES;                              \
        cpasync16(s_ + dAh +  8192, pAh + (ko) + (size_t)64 * IN_DIM);       \
        cpasync16(s_ + dAl +  8192, pAl + (ko) + (size_t)64 * IN_DIM);       \
        cpasync16(s_ + dAh + 12288, pAh + (ko) + (size_t)96 * IN_DIM);       \
        cpasync16(s_ + dAl + 12288, pAl + (ko) + (size_t)96 * IN_DIM);       \
    } while (0)
#define ISSUE_B(stg, ko)                                                     \
    do {                                                                     \
        uint32_t s_ = sb + (stg) * STAGE_BYTES;                              \
        cpasync16(s_ + dBh,        pBh + (ko));                              \
        cpasync16(s_ + dBl,        pBl + (ko));                              \
        cpasync16(s_ + dBh + 4096, pBh + (ko) + (size_t)32 * IN_DIM);        \
        cpasync16(s_ + dBl + 4096, pBl + (ko) + (size_t)32 * IN_DIM);        \
    } while (0)

    float acc[2][4][4];
#pragma unroll
    for (int i = 0; i < 2; i++)
#pragma unroll
        for (int j = 0; j < 4; j++)
#pragma unroll
            for (int q = 0; q < 4; q++) acc[i][j][q] = 0.0f;

    // Per-lane ldmatrix logical coordinates (ks phase 0..3 -> cc = ks*2 + ch)
    const int a_rl = lane & 15;               // A: rows m0..m0+15
    const int a_ch = lane >> 4;               // A: +0 / +1 chunk
    const int b4_row = ((lane >> 4) << 3) + (lane & 7);   // B x4 ni-pair
    const int b4_c   = (lane >> 3) & 1;

    uint32_t oA[4][2], oB[4][2];              // [ks][mi] / [ks][nj]
#pragma unroll
    for (int ks = 0; ks < 4; ks++) {
#pragma unroll
        for (int mi = 0; mi < 2; mi++)
            oA[ks][mi] = swz128(0, wm * 32 + mi * 16 + a_rl, ks * 2 + a_ch);
#pragma unroll
        for (int nj = 0; nj < 2; nj++)
            oB[ks][nj] = swz128(0, wn * 32 + nj * 16 + b4_row, ks * 2 + b4_c);
    }

    // Fragment registers: hi double-buffered, lo just-in-time
    uint32_t ah0[2][4], ah1[2][4];
    uint32_t bh0[4][2], bh1[4][2];
    uint32_t al[2][4],  bl[4][2];

#define LOAD_HI(AH, BH, SBASE, KS)                                           \
    do {                                                                     \
        LDSM_X4(AH[0],     (SBASE) + AHI + oA[KS][0]);                       \
        LDSM_X4(AH[1],     (SBASE) + AHI + oA[KS][1]);                       \
        LDSM_X4(&BH[0][0], (SBASE) + BHI + oB[KS][0]);                       \
        LDSM_X4(&BH[2][0], (SBASE) + BHI + oB[KS][1]);                       \
    } while (0)

#define LOAD_LO(SBASE, KS)                                                   \
    do {                                                                     \
        LDSM_X4(al[0],     (SBASE) + ALO + oA[KS][0]);                       \
        LDSM_X4(al[1],     (SBASE) + ALO + oA[KS][1]);                       \
        LDSM_X4(&bl[0][0], (SBASE) + BLO + oB[KS][0]);                       \
        LDSM_X4(&bl[2][0], (SBASE) + BLO + oB[KS][1]);                       \
    } while (0)

#define MMA_PHASE(AH, BH)                                                    \
    do {                                                                     \
        _Pragma("unroll")                                                    \
        for (int mi = 0; mi < 2; mi++)                                       \
            _Pragma("unroll")                                                \
            for (int ni = 0; ni < 4; ni++)                                   \
                MMA16816(acc[mi][ni], AH[mi], BH[ni]);                       \
        _Pragma("unroll")                                                    \
        for (int mi = 0; mi < 2; mi++)                                       \
            _Pragma("unroll")                                                \
            for (int ni = 0; ni < 4; ni++)                                   \
                MMA16816(acc[mi][ni], AH[mi], bl[ni]);                       \
        _Pragma("unroll")                                                    \
        for (int mi = 0; mi < 2; mi++)                                       \
            _Pragma("unroll")                                                \
            for (int ni = 0; ni < 4; ni++)                                   \
                MMA16816(acc[mi][ni], al[mi], BH[ni]);                       \
    } while (0)

    // Prologue: chunk 0 -> stage 0
    ISSUE_A0(0, 0);
    ISSUE_A1(0, 0);
    ISSUE_B(0, 0);
    CP_COMMIT();

    size_t kload = BK;                  // element offset of the NEXT chunk

#pragma unroll 1
    for (int kt = 0; kt < NKT; kt++) {
        CP_WAIT0();
        __syncthreads();

        const uint32_t s_cur = sb + (kt & 1) * STAGE_BYTES;
        const uint32_t s_oth = (kt + 1) & 1;
        const bool refill = (kt + 1 < NKT);

        // phase 0 hi (only exposed LDSM of the chunk; other CTA covers)
        LOAD_HI(ah0, bh0, s_cur, 0);

        // ---- phase 0 ----
        LOAD_LO(s_cur, 0);
        LOAD_HI(ah1, bh1, s_cur, 1);
        MMA_PHASE(ah0, bh0);

        if (refill) { ISSUE_A0(s_oth, kload); CP_COMMIT(); }

        // ---- phase 1 ----
        LOAD_LO(s_cur, 1);
        LOAD_HI(ah0, bh0, s_cur, 2);
        MMA_PHASE(ah1, bh1);

        if (refill) { ISSUE_A1(s_oth, kload); CP_COMMIT(); }

        // ---- phase 2 ----
        LOAD_LO(s_cur, 2);
        LOAD_HI(ah1, bh1, s_cur, 3);
        MMA_PHASE(ah0, bh0);

        if (refill) { ISSUE_B(s_oth, kload); CP_COMMIT(); kload += BK; }

        // ---- phase 3 ----
        LOAD_LO(s_cur, 3);
        MMA_PHASE(ah1, bh1);
    }

    // ------------------- epilogue: +pb, tanh, store -------------------
    float pbv[4][2];
#pragma unroll
    for (int ni = 0; ni < 4; ni++) {
        const int col = bn + wn * 32 + ni * 8 + tg * 2;
        pbv[ni][0] = g_pb[col];
        pbv[ni][1] = g_pb[col + 1];
    }
#pragma unroll
    for (int mi = 0; mi < 2; mi++) {
        const int r = bm + wm * 32 + mi * 16 + gid;
#pragma unroll
        for (int ni = 0; ni < 4; ni++) {
            const int col = bn + wn * 32 + ni * 8 + tg * 2;
            float2 v0, v1;
            v0.x = tanhf(acc[mi][ni][0] + pbv[ni][0]);
            v0.y = tanhf(acc[mi][ni][1] + pbv[ni][1]);
            v1.x = tanhf(acc[mi][ni][2] + pbv[ni][0]);
            v1.y = tanhf(acc[mi][ni][3] + pbv[ni][1]);
            *(float2*)(out + (size_t)r * OUT_DIM + col)       = v0;
            *(float2*)(out + (size_t)(r + 8) * OUT_DIM + col) = v1;
        }
    }
}

// ---------------------------------------------------------------------------
// Host launch
// ---------------------------------------------------------------------------
extern "C" void kernel_launch(void* const* d_in, const int* in_sizes, int n_in,
                              void* d_out, int out_size) {
    const float *x = nullptr, *uw = nullptr, *cw = nullptr, *cb = nullptr;
    for (int i = 0; i < n_in; i++) {
        switch (in_sizes[i]) {
            case BATCH * IN_DIM:           x  = (const float*)d_in[i]; break;
            case DEPTH * IN_DIM * OUT_DIM: uw = (const float*)d_in[i]; break;
            case IN_DIM * OUT_DIM:         cw = (const float*)d_in[i]; break;
            case OUT_DIM:                  cb = (const float*)d_in[i]; break;
            default: break;
        }
    }
    float* out = (float*)d_out;

    prep_kernel<<<PREP_BLOCKS, 256>>>(x, cw, uw, cb);

    static int attr_done = 0;
    if (!attr_done) {
        cudaFuncSetAttribute(gemm_bf16x3_kernel,
                             cudaFuncAttributeMaxDynamicSharedMemorySize,
                             SMEM_TOTAL);
        attr_done = 1;
    }
    dim3 grid(OUT_DIM / BN, BATCH / BM);   // (32, 64)
    gemm_bf16x3_kernel<<<grid, 256, SMEM_TOTAL>>>(out);
}

// round 17
// speedup vs baseline: 1.0227x; 1.0227x over previous
#include <cuda_runtime.h>
#include <cuda_bf16.h>
#include <math.h>
#include <stdint.h>

// ---------------------------------------------------------------------------
// Problem constants
// ---------------------------------------------------------------------------
#define BATCH   8192
#define IN_DIM  4096
#define OUT_DIM 2048
#define DEPTH   9
#define RSTEPS  27
#define WIN     55
#define CENTER  27

// GEMM tiling: 128x64 CTA tile, BK=64, 2-stage ring, 2 CTAs/SM
#define BM 128
#define BN 64
#define BK 64
#define NKT (IN_DIM / BK)            // 64
#define STAGES 2
// Stage layout (128B rows): Ahi 16K | Alo 16K | Bhi 8K | Blo 8K
#define AHI 0
#define ALO 16384
#define BHI 32768
#define BLO 40960
#define STAGE_BYTES 49152
#define SMEM_TOTAL (STAGES * STAGE_BYTES)   // 98304/CTA -> 2 CTAs = 192KB/SM

// ---------------------------------------------------------------------------
// Device-global scratch (static: no runtime allocation)
// ---------------------------------------------------------------------------
__device__ float         g_pb[OUT_DIM];
__device__ __nv_bfloat16 g_xhi[(size_t)BATCH * IN_DIM];
__device__ __nv_bfloat16 g_xlo[(size_t)BATCH * IN_DIM];
__device__ __nv_bfloat16 g_wThi[(size_t)OUT_DIM * IN_DIM];   // W^T [N][K]
__device__ __nv_bfloat16 g_wTlo[(size_t)OUT_DIM * IN_DIM];

// ---------------------------------------------------------------------------
// PTX helpers (base sm_103 ISA only: cp.async / ldmatrix / mma.sync)
// ---------------------------------------------------------------------------
__device__ __forceinline__ uint32_t smem_u32(const void* p) {
    uint32_t a;
    asm("{ .reg .u64 t; cvta.to.shared.u64 t, %1; cvt.u32.u64 %0, t; }"
        : "=r"(a) : "l"(p));
    return a;
}
__device__ __forceinline__ void cpasync16(uint32_t dst, const void* src) {
    asm volatile("cp.async.cg.shared.global [%0], [%1], 16;"
                 :: "r"(dst), "l"(src));
}
#define CP_COMMIT() asm volatile("cp.async.commit_group;" ::: "memory")
#define CP_WAIT0()  asm volatile("cp.async.wait_group 0;"  ::: "memory")

#define LDSM_X4(d, a) \
    asm volatile("ldmatrix.sync.aligned.m8n8.x4.shared.b16 {%0,%1,%2,%3}, [%4];" \
        : "=r"((d)[0]), "=r"((d)[1]), "=r"((d)[2]), "=r"((d)[3]) : "r"(a))

#define MMA16816(c, a, b) \
    asm volatile("mma.sync.aligned.m16n8k16.row.col.f32.bf16.bf16.f32 " \
        "{%0,%1,%2,%3}, {%4,%5,%6,%7}, {%8,%9}, {%0,%1,%2,%3};" \
        : "+f"((c)[0]), "+f"((c)[1]), "+f"((c)[2]), "+f"((c)[3]) \
        : "r"((a)[0]), "r"((a)[1]), "r"((a)[2]), "r"((a)[3]), \
          "r"((b)[0]), "r"((b)[1]))

// SW128 swizzle for 128B physical rows: row r, 16B-chunk cc in 0..7.
__device__ __forceinline__ uint32_t swz128(uint32_t base, int row, int cc) {
    return base + row * 128 + (((cc) ^ (row & 7)) << 4);
}

// ---------------------------------------------------------------------------
// Fused prepass kernel: one launch, roles by blockIdx.x range.
//   [0, 16384)            split x -> (hi, lo) bf16   (8 elems/thread, 16B stores)
//   [16384, 24576)        transpose+split W -> wT hi/lo (4-wide 8B stores)
//   [24576, 24584)        universal probs + bias -> g_pb
// ---------------------------------------------------------------------------
#define SPLITX_BLOCKS 16384   // (8192*4096)/(8*256)
#define SPLITW_BLOCKS 8192    // (2048/32)*(4096/32)
#define PROBS_BLOCKS  8
#define PREP_BLOCKS   (SPLITX_BLOCKS + SPLITW_BLOCKS + PROBS_BLOCKS)

__device__ __forceinline__ uint32_t split_pair(float a, float b, uint32_t* lo) {
    __nv_bfloat16 ha = __float2bfloat16(a);
    __nv_bfloat16 hb = __float2bfloat16(b);
    __nv_bfloat162 hp(ha, hb);
    __nv_bfloat162 lp(__float2bfloat16(a - __bfloat162float(ha)),
                      __float2bfloat16(b - __bfloat162float(hb)));
    *lo = *(uint32_t*)&lp;
    return *(uint32_t*)&hp;
}

__global__ __launch_bounds__(256)
void prep_kernel(const float* __restrict__ x,
                 const float* __restrict__ W,
                 const float* __restrict__ uw,
                 const float* __restrict__ bias) {
    __shared__ float t[32][33];
    const int b   = blockIdx.x;
    const int tid = threadIdx.x;

    if (b < SPLITX_BLOCKS) {
        // ---- split x: 8 elements/thread, 16B hi store + 16B lo store ----
        size_t i = ((size_t)b * 256 + tid) * 8;
        float4 v0 = *(const float4*)(x + i);
        float4 v1 = *(const float4*)(x + i + 4);
        uint4 hi, lo;
        hi.x = split_pair(v0.x, v0.y, &lo.x);
        hi.y = split_pair(v0.z, v0.w, &lo.y);
        hi.z = split_pair(v1.x, v1.y, &lo.z);
        hi.w = split_pair(v1.z, v1.w, &lo.w);
        *(uint4*)(g_xhi + i) = hi;
        *(uint4*)(g_xlo + i) = lo;
    } else if (b < SPLITX_BLOCKS + SPLITW_BLOCKS) {
        // ---- transpose + split W (vectorized output: 4 k per thread) ----
        const int bw = b - SPLITX_BLOCKS;
        const int n0 = (bw & 63) * 32;
        const int k0 = (bw >> 6) * 32;
        const int tx = tid & 31, ty = tid >> 5;   // 32 x 8 load mapping
#pragma unroll
        for (int i = 0; i < 32; i += 8)
            t[ty + i][tx] = W[(size_t)(k0 + ty + i) * OUT_DIM + n0 + tx];
        __syncthreads();
        // Store mapping: thread = (row n = tid&31, k-quad q = tid>>5)
        const int n = tid & 31;
        const int q = (tid >> 5) * 4;             // k offset 0,4,...,28
        uint32_t h2[2], l2[2];
#pragma unroll
        for (int j = 0; j < 2; j++) {
            float a = t[q + j * 2][n];
            float c = t[q + j * 2 + 1][n];
            h2[j] = split_pair(a, c, &l2[j]);
        }
        size_t o = (size_t)(n0 + n) * IN_DIM + k0 + q;
        *(uint2*)(g_wThi + o) = make_uint2(h2[0], h2[1]);
        *(uint2*)(g_wTlo + o) = make_uint2(l2[0], l2[1]);
    } else {
        // ---- universal probs (dependency-cone trick) ----
        const int o = (b - SPLITX_BLOCKS - SPLITW_BLOCKS) * 256 + tid;
        if (o >= OUT_DIM) return;
        float w[WIN];
#pragma unroll
        for (int j = 0; j < WIN; j++) w[j] = 0.015625f;   // 1/sqrt(4096)
#pragma unroll
        for (int s = 0; s < RSTEPS; s++) {
            const int d = s / 3, g = s % 3;
            float ang = uw[(size_t)d * IN_DIM * OUT_DIM + (size_t)o * OUT_DIM + g];
            float sn, cs;
            sincosf(ang, &sn, &cs);
            float nw[WIN];
            nw[0] = w[0]; nw[WIN - 1] = w[WIN - 1];
#pragma unroll
            for (int j = 1; j < WIN - 1; j++)
                nw[j] = cs * w[j] - sn * w[j + 1] + sn * w[j - 1];
#pragma unroll
            for (int j = 0; j < WIN; j++) w[j] = nw[j];
        }
        g_pb[o] = w[CENTER] * w[CENTER] + bias[o];
    }
}

// ---------------------------------------------------------------------------
// GEMM kernel: C = tanh(x @ W + g_pb) via bf16x3 mma.sync.  (R15 pipeline)
// 128x64x64 chunks, 2-stage ring, 2 CTAs/SM, 8 warps, warp tile 32x32.
// ONE wait0+__syncthreads per BK=64 chunk; no cross-stage reads; refill
// split into A-half (after phase 0) and B-half (after phase 1) with a
// SINGLE commit per chunk. R17 delta: running-pointer refill addressing
// (pointers advanced by BK per chunk; no per-chunk offset multiplies).
// ---------------------------------------------------------------------------
__global__ __launch_bounds__(256, 2)
void gemm_bf16x3_kernel(float* __restrict__ out) {
    extern __shared__ char smem[];
    const uint32_t sb = smem_u32(smem);

    const int tid  = threadIdx.x;
    const int lane = tid & 31;
    const int wid  = tid >> 5;
    const int wm   = wid >> 1;          // 0..3  -> m offset wm*32
    const int wn   = wid & 1;           // 0..1  -> n offset wn*32
    const int gid  = lane >> 2;
    const int tg   = lane & 3;
    const int bm   = blockIdx.y * BM;
    const int bn   = blockIdx.x * BN;

    // --- global load mapping: 12 x 16B chunks per thread per BK=64 chunk ---
    const int r0 = tid >> 3;            // 0..31
    const int cA = tid & 7;             // 16B chunk in 128B row

    // Running pointers: advanced by BK once per chunk (strength-reduced).
    const __nv_bfloat16* pAh = g_xhi  + (size_t)(bm + r0) * IN_DIM + cA * 8;
    const __nv_bfloat16* pAl = g_xlo  + (size_t)(bm + r0) * IN_DIM + cA * 8;
    const __nv_bfloat16* pBh = g_wThi + (size_t)(bn + r0) * IN_DIM + cA * 8;
    const __nv_bfloat16* pBl = g_wTlo + (size_t)(bn + r0) * IN_DIM + cA * 8;

    const uint32_t dAh = swz128(AHI, r0, cA);
    const uint32_t dAl = swz128(ALO, r0, cA);
    const uint32_t dBh = swz128(BHI, r0, cA);
    const uint32_t dBl = swz128(BLO, r0, cA);

#define ISSUE_A(stg)                                                         \
    do {                                                                     \
        uint32_t s_ = sb + (stg) * STAGE_BYTES;                              \
        _Pragma("unroll")                                                    \
        for (int i = 0; i < 4; i++) {                                        \
            cpasync16(s_ + dAh + i * 4096, pAh + (size_t)i * 32 * IN_DIM);   \
            cpasync16(s_ + dAl + i * 4096, pAl + (size_t)i * 32 * IN_DIM);   \
        }                                                                    \
    } while (0)

#define ISSUE_B(stg)                                                         \
    do {                                                                     \
        uint32_t s_ = sb + (stg) * STAGE_BYTES;                              \
        _Pragma("unroll")                                                    \
        for (int i = 0; i < 2; i++) {                                        \
            cpasync16(s_ + dBh + i * 4096, pBh + (size_t)i * 32 * IN_DIM);   \
            cpasync16(s_ + dBl + i * 4096, pBl + (size_t)i * 32 * IN_DIM);   \
        }                                                                    \
    } while (0)

    float acc[2][4][4];
#pragma unroll
    for (int i = 0; i < 2; i++)
#pragma unroll
        for (int j = 0; j < 4; j++)
#pragma unroll
            for (int q = 0; q < 4; q++) acc[i][j][q] = 0.0f;

    // Per-lane ldmatrix logical coordinates (ks phase 0..3 -> cc = ks*2 + ch)
    const int a_rl = lane & 15;               // A: rows m0..m0+15
    const int a_ch = lane >> 4;               // A: +0 / +1 chunk
    const int b4_row = ((lane >> 4) << 3) + (lane & 7);   // B x4 ni-pair
    const int b4_c   = (lane >> 3) & 1;

    uint32_t oA[4][2], oB[4][2];              // [ks][mi] / [ks][nj]
#pragma unroll
    for (int ks = 0; ks < 4; ks++) {
#pragma unroll
        for (int mi = 0; mi < 2; mi++)
            oA[ks][mi] = swz128(0, wm * 32 + mi * 16 + a_rl, ks * 2 + a_ch);
#pragma unroll
        for (int nj = 0; nj < 2; nj++)
            oB[ks][nj] = swz128(0, wn * 32 + nj * 16 + b4_row, ks * 2 + b4_c);
    }

    // Fragment registers: hi double-buffered, lo just-in-time
    uint32_t ah0[2][4], ah1[2][4];
    uint32_t bh0[4][2], bh1[4][2];
    uint32_t al[2][4],  bl[4][2];

#define LOAD_HI(AH, BH, SBASE, KS)                                           \
    do {                                                                     \
        LDSM_X4(AH[0],     (SBASE) + AHI + oA[KS][0]);                       \
        LDSM_X4(AH[1],     (SBASE) + AHI + oA[KS][1]);                       \
        LDSM_X4(&BH[0][0], (SBASE) + BHI + oB[KS][0]);                       \
        LDSM_X4(&BH[2][0], (SBASE) + BHI + oB[KS][1]);                       \
    } while (0)

#define LOAD_LO(SBASE, KS)                                                   \
    do {                                                                     \
        LDSM_X4(al[0],     (SBASE) + ALO + oA[KS][0]);                       \
        LDSM_X4(al[1],     (SBASE) + ALO + oA[KS][1]);                       \
        LDSM_X4(&bl[0][0], (SBASE) + BLO + oB[KS][0]);                       \
        LDSM_X4(&bl[2][0], (SBASE) + BLO + oB[KS][1]);                       \
    } while (0)

#define MMA_PHASE(AH, BH)                                                    \
    do {                                                                     \
        _Pragma("unroll")                                                    \
        for (int mi = 0; mi < 2; mi++)                                       \
            _Pragma("unroll")                                                \
            for (int ni = 0; ni < 4; ni++)                                   \
                MMA16816(acc[mi][ni], AH[mi], BH[ni]);                       \
        _Pragma("unroll")                                                    \
        for (int mi = 0; mi < 2; mi++)                                       \
            _Pragma("unroll")                                                \
            for (int ni = 0; ni < 4; ni++)                                   \
                MMA16816(acc[mi][ni], AH[mi], bl[ni]);                       \
        _Pragma("unroll")                                                    \
        for (int mi = 0; mi < 2; mi++)                                       \
            _Pragma("unroll")                                                \
            for (int ni = 0; ni < 4; ni++)                                   \
                MMA16816(acc[mi][ni], al[mi], BH[ni]);                       \
    } while (0)

    // Prologue: chunk 0 -> stage 0, then advance pointers to chunk 1
    ISSUE_A(0);
    ISSUE_B(0);
    CP_COMMIT();
    pAh += BK; pAl += BK; pBh += BK; pBl += BK;

#pragma unroll 1
    for (int kt = 0; kt < NKT; kt++) {
        CP_WAIT0();
        __syncthreads();

        const uint32_t s_cur = sb + (kt & 1) * STAGE_BYTES;
        const uint32_t s_oth = (kt + 1) & 1;
        const bool refill = (kt + 1 < NKT);

        // phase 0 hi (only exposed LDSM of the chunk; other CTA covers)
        LOAD_HI(ah0, bh0, s_cur, 0);

        // ---- phase 0 ----
        LOAD_LO(s_cur, 0);
        LOAD_HI(ah1, bh1, s_cur, 1);
        MMA_PHASE(ah0, bh0);

        // Refill A-half: chunk kt+1 -> other stage (consumed at kt-1; the
        // top barrier of this iteration protects it).
        if (refill) ISSUE_A(s_oth);

        // ---- phase 1 ----
        LOAD_LO(s_cur, 1);
        LOAD_HI(ah0, bh0, s_cur, 2);
        MMA_PHASE(ah1, bh1);

        // Refill B-half + single commit (one commit per chunk; wait0 at
        // the next top covers both halves).
        if (refill) {
            ISSUE_B(s_oth);
            CP_COMMIT();
            pAh += BK; pAl += BK; pBh += BK; pBl += BK;
        }

        // ---- phase 2 ----
        LOAD_LO(s_cur, 2);
        LOAD_HI(ah1, bh1, s_cur, 3);
        MMA_PHASE(ah0, bh0);

        // ---- phase 3 ----
        LOAD_LO(s_cur, 3);
        MMA_PHASE(ah1, bh1);
    }

    // ------------------- epilogue: +pb, tanh, store -------------------
    float pbv[4][2];
#pragma unroll
    for (int ni = 0; ni < 4; ni++) {
        const int col = bn + wn * 32 + ni * 8 + tg * 2;
        pbv[ni][0] = g_pb[col];
        pbv[ni][1] = g_pb[col + 1];
    }
#pragma unroll
    for (int mi = 0; mi < 2; mi++) {
        const int r = bm + wm * 32 + mi * 16 + gid;
#pragma unroll
        for (int ni = 0; ni < 4; ni++) {
            const int col = bn + wn * 32 + ni * 8 + tg * 2;
            float2 v0, v1;
            v0.x = tanhf(acc[mi][ni][0] + pbv[ni][0]);
            v0.y = tanhf(acc[mi][ni][1] + pbv[ni][1]);
            v1.x = tanhf(acc[mi][ni][2] + pbv[ni][0]);
            v1.y = tanhf(acc[mi][ni][3] + pbv[ni][1]);
            *(float2*)(out + (size_t)r * OUT_DIM + col)       = v0;
            *(float2*)(out + (size_t)(r + 8) * OUT_DIM + col) = v1;
        }
    }
}

// ---------------------------------------------------------------------------
// Host launch
// ---------------------------------------------------------------------------
extern "C" void kernel_launch(void* const* d_in, const int* in_sizes, int n_in,
                              void* d_out, int out_size) {
    const float *x = nullptr, *uw = nullptr, *cw = nullptr, *cb = nullptr;
    for (int i = 0; i < n_in; i++) {
        switch (in_sizes[i]) {
            case BATCH * IN_DIM:           x  = (const float*)d_in[i]; break;
            case DEPTH * IN_DIM * OUT_DIM: uw = (const float*)d_in[i]; break;
            case IN_DIM * OUT_DIM:         cw = (const float*)d_in[i]; break;
            case OUT_DIM:                  cb = (const float*)d_in[i]; break;
            default: break;
        }
    }
    float* out = (float*)d_out;

    prep_kernel<<<PREP_BLOCKS, 256>>>(x, cw, uw, cb);

    static int attr_done = 0;
    if (!attr_done) {
        cudaFuncSetAttribute(gemm_bf16x3_kernel,
                             cudaFuncAttributeMaxDynamicSharedMemorySize,
                             SMEM_TOTAL);
        attr_done = 1;
    }
    dim3 grid(OUT_DIM / BN, BATCH / BM);   // (32, 64)
    gemm_bf16x3_kernel<<<grid, 256, SMEM_TOTAL>>>(out);
}